// round 14
// baseline (speedup 1.0000x reference)
#include <cuda_runtime.h>
#include <cuda_fp16.h>
#include <cstdint>

// Problem constants: B=C=P=D=256
#define N256 256
#define EPS 1e-5f

// ---------------- scratch (device globals; no allocations allowed) ----------
__device__ __half2 g_xembh[256 * 128 * 256]; // [b][c/2][d] k-pair-packed halves
__device__ __half2 g_maskh[256 * 128];       // [p][c/2] k-pair-packed halves
__device__ float g_xprompt[256 * 256];       // [P,D]
__device__ float g_logits[256 * 256];        // [P,C]
__device__ int g_cnt[16];                    // arrival counters (zero-init, self-resetting)

// ---------------- helpers ----------------------------------------------------
__device__ __forceinline__ void cp_async16(void* smem, const void* gmem) {
    uint32_t s = (uint32_t)__cvta_generic_to_shared(smem);
    asm volatile("cp.async.cg.shared.global [%0], [%1], 16;" :: "r"(s), "l"(gmem));
}
__device__ __forceinline__ void cp_commit() {
    asm volatile("cp.async.commit_group;" ::: "memory");
}
template <int N>
__device__ __forceinline__ void cp_wait() {
    asm volatile("cp.async.wait_group %0;" :: "n"(N) : "memory");
}
__device__ __forceinline__ void ldsm_x4(uint32_t& r0, uint32_t& r1,
                                        uint32_t& r2, uint32_t& r3,
                                        const void* smem_ptr) {
    uint32_t a = (uint32_t)__cvta_generic_to_shared(smem_ptr);
    asm volatile("ldmatrix.sync.aligned.m8n8.x4.shared.b16 {%0,%1,%2,%3}, [%4];"
                 : "=r"(r0), "=r"(r1), "=r"(r2), "=r"(r3) : "r"(a));
}

// LN stats for NR rows, 8 threads per row (threads t < NR*8).
template <int NR>
__device__ __forceinline__ void row_stats(const float* __restrict__ src,
                                          int row0, float* smu, float* srs,
                                          int t) {
    if (t < NR * 8) {
        int r = t >> 3, j = t & 7;
        const float4* base4 = (const float4*)(src + (row0 + r) * 256);
        float s = 0.f, q = 0.f;
#pragma unroll
        for (int i = 0; i < 8; i++) {
            float4 v = base4[j + i * 8];
            s += v.x + v.y + v.z + v.w;
            q = fmaf(v.x, v.x, q); q = fmaf(v.y, v.y, q);
            q = fmaf(v.z, v.z, q); q = fmaf(v.w, v.w, q);
        }
#pragma unroll
        for (int off = 4; off > 0; off >>= 1) {
            s += __shfl_xor_sync(0xffffffffu, s, off, 8);
            q += __shfl_xor_sync(0xffffffffu, q, off, 8);
        }
        if (j == 0) {
            float mu = s * (1.f / 256.f);
            smu[r] = mu;
            srs[r] = rsqrtf(q * (1.f / 256.f) - mu * mu + EPS);
        }
    }
}

// ---------------- K1: xemb pairs (grid 4096) ---------------------------------
__global__ void xemb_kernel(const float* __restrict__ x,
                            const float* __restrict__ few,
                            const float* __restrict__ feb,
                            const float* __restrict__ lnew,
                            const float* __restrict__ lneb) {
    __shared__ float sbuf[6 * 256];
    int tid = threadIdx.x;
    float* sw0 = sbuf;
    float* sb0 = sbuf + 256;
    float* sw1 = sbuf + 512;
    float* sb1 = sbuf + 768;
    float* slw = sbuf + 1024;
    float* slb = sbuf + 1280;
    int c2 = blockIdx.x >> 5;
    int bg = blockIdx.x & 31;
    int c0 = c2 * 2, c1 = c0 + 1;
    sw0[tid] = few[c0 * 256 + tid];
    sb0[tid] = feb[c0 * 256 + tid];
    sw1[tid] = few[c1 * 256 + tid];
    sb1[tid] = feb[c1 * 256 + tid];
    slw[tid] = lnew[tid];
    slb[tid] = lneb[tid];
    __syncthreads();

    int lane = tid & 31;
    int wid = tid >> 5;
    int b = bg * 8 + wid;
    float xv0 = x[b * 256 + c0];
    float xv1 = x[b * 256 + c1];
    float v0[8], v1[8];
    float s0 = 0.f, q0 = 0.f, s1 = 0.f, q1 = 0.f;
#pragma unroll
    for (int i = 0; i < 8; i++) {
        int d = lane + i * 32;
        float t0 = fmaf(xv0, sw0[d], sb0[d]);
        float t1 = fmaf(xv1, sw1[d], sb1[d]);
        t0 = t0 > 0.f ? t0 : 0.f;
        t1 = t1 > 0.f ? t1 : 0.f;
        v0[i] = t0; v1[i] = t1;
        s0 += t0; q0 = fmaf(t0, t0, q0);
        s1 += t1; q1 = fmaf(t1, t1, q1);
    }
#pragma unroll
    for (int off = 16; off > 0; off >>= 1) {
        s0 += __shfl_xor_sync(0xffffffff, s0, off);
        q0 += __shfl_xor_sync(0xffffffff, q0, off);
        s1 += __shfl_xor_sync(0xffffffff, s1, off);
        q1 += __shfl_xor_sync(0xffffffff, q1, off);
    }
    float mu0 = s0 * (1.f / 256.f);
    float rs0 = rsqrtf(q0 * (1.f / 256.f) - mu0 * mu0 + EPS);
    float mu1 = s1 * (1.f / 256.f);
    float rs1 = rsqrtf(q1 * (1.f / 256.f) - mu1 * mu1 + EPS);
    __half2* orow = g_xembh + ((long)b * 128 + c2) * 256;
#pragma unroll
    for (int i = 0; i < 8; i++) {
        int d = lane + i * 32;
        float o0 = (v0[i] - mu0) * rs0 * slw[d] + slb[d];
        float o1 = (v1[i] - mu1) * rs1 * slw[d] + slb[d];
        orow[d] = __floats2half2_rn(o0, o1);
    }
}

// ---------------- K2: x_prompt = [LN(embp)|prev] @ W^T + b + embp -----------
// Tile 16(p) x 32(d), grid (8,16) = 128 blocks. LN fused, reg double-buffered.
__global__ void xprompt_fused(const float* __restrict__ W,
                              const float* __restrict__ bias,
                              const float* __restrict__ embp,
                              const float* __restrict__ lnpw,
                              const float* __restrict__ lnpb,
                              const float* __restrict__ prev) {
    __shared__ float As[16][17];
    __shared__ float Ws[32][17];
    __shared__ float smu[16], srs[16];
    int tx = threadIdx.x, ty = threadIdx.y;
    int t = ty * 16 + tx;
    int p0 = blockIdx.y * 16;
    int d0 = blockIdx.x * 32;

    row_stats<16>(embp, p0, smu, srs, t);
    __syncthreads();

    int ra = t >> 4, ka = t & 15;     // As coord (1 elem)
    int rw1 = 16 + ra;                // Ws second row

    auto fetch = [&](int kt, float& v, float* w) {
        int gk = kt * 16 + ka;
        v = (gk < 256)
          ? (embp[(p0 + ra) * 256 + gk] - smu[ra]) * srs[ra] * lnpw[gk] + lnpb[gk]
          : prev[(p0 + ra) * 256 + gk - 256];
        w[0] = W[(d0 + ra) * 512 + gk];
        w[1] = W[(d0 + rw1) * 512 + gk];
    };

    float va, wa[2], vb, wb[2];
    fetch(0, va, wa);

    float acc[2] = {0.f, 0.f};
    for (int kt = 0; kt < 32; kt++) {
        As[ra][ka] = va;
        Ws[ra][ka] = wa[0];
        Ws[rw1][ka] = wa[1];
        __syncthreads();
        if (kt < 31) fetch(kt + 1, vb, wb);
#pragma unroll
        for (int kk = 0; kk < 16; kk++) {
            float a = As[ty][kk];
            acc[0] = fmaf(a, Ws[tx * 2][kk], acc[0]);
            acc[1] = fmaf(a, Ws[tx * 2 + 1][kk], acc[1]);
        }
        __syncthreads();
        va = vb; wa[0] = wb[0]; wa[1] = wb[1];
    }
    int p = p0 + ty;
#pragma unroll
    for (int j = 0; j < 2; j++) {
        int dd = d0 + tx * 2 + j;
        g_xprompt[p * N256 + dd] = acc[j] + bias[dd] + embp[p * N256 + dd];
    }
}

// ---------------- K3: logits = x_prompt @ LN(embc)^T, softmax fused ----------
// Tile 16(p) x 32(c), grid (8,16) = 128 blocks.
__global__ void logits_fused(const float* __restrict__ embc,
                             const float* __restrict__ lncw,
                             const float* __restrict__ lncb) {
    __shared__ float As[16][17];
    __shared__ float Bs[32][17];
    __shared__ float smu[32], srs[32];
    __shared__ int sflag;
    int tx = threadIdx.x, ty = threadIdx.y;
    int t = ty * 16 + tx;
    int p0 = blockIdx.y * 16;
    int c0 = blockIdx.x * 32;

    row_stats<32>(embc, c0, smu, srs, t);
    __syncthreads();

    int ra = t >> 4, ka = t & 15;
    int rb1 = 16 + ra;

    auto fetch = [&](int kt, float& a, float* b) {
        int gk = kt * 16 + ka;
        a = g_xprompt[(p0 + ra) * N256 + gk];
        b[0] = (embc[(c0 + ra) * 256 + gk] - smu[ra]) * srs[ra] * lncw[gk] + lncb[gk];
        b[1] = (embc[(c0 + rb1) * 256 + gk] - smu[rb1]) * srs[rb1] * lncw[gk] + lncb[gk];
    };

    float aa, ba[2], ab, bb[2];
    fetch(0, aa, ba);

    float acc[2] = {0.f, 0.f};
    for (int kt = 0; kt < 16; kt++) {
        As[ra][ka] = aa;
        Bs[ra][ka] = ba[0];
        Bs[rb1][ka] = ba[1];
        __syncthreads();
        if (kt < 15) fetch(kt + 1, ab, bb);
#pragma unroll
        for (int kk = 0; kk < 16; kk++) {
            float a = As[ty][kk];
            acc[0] = fmaf(a, Bs[tx * 2][kk], acc[0]);
            acc[1] = fmaf(a, Bs[tx * 2 + 1][kk], acc[1]);
        }
        __syncthreads();
        aa = ab; ba[0] = bb[0]; ba[1] = bb[1];
    }
    int p = p0 + ty;
#pragma unroll
    for (int j = 0; j < 2; j++)
        g_logits[p * N256 + c0 + tx * 2 + j] = acc[j];

    // arrival counting: 8 blocks per 16-row p-group
    __threadfence();
    __syncthreads();
    if (t == 0) {
        int old = atomicAdd(&g_cnt[blockIdx.y], 1);
        sflag = (old == 7);
    }
    __syncthreads();
    if (!sflag) return;

    // finisher: softmax for rows p0..p0+15 (8 warps x 2 rows)
    int lane = t & 31;
    int warp = t >> 5;
#pragma unroll
    for (int q = 0; q < 2; q++) {
        int pr = p0 + warp * 2 + q;
        const float* row = g_logits + pr * N256;
        float4 v0 = *(const float4*)(row + lane * 4);
        float4 v1 = *(const float4*)(row + 128 + lane * 4);
        float m = fmaxf(fmaxf(fmaxf(v0.x, v0.y), fmaxf(v0.z, v0.w)),
                        fmaxf(fmaxf(v1.x, v1.y), fmaxf(v1.z, v1.w)));
#pragma unroll
        for (int off = 16; off > 0; off >>= 1)
            m = fmaxf(m, __shfl_xor_sync(0xffffffff, m, off));
        float e0 = expf(v0.x - m), e1 = expf(v0.y - m);
        float e2 = expf(v0.z - m), e3 = expf(v0.w - m);
        float f0 = expf(v1.x - m), f1 = expf(v1.y - m);
        float f2 = expf(v1.z - m), f3 = expf(v1.w - m);
        float s = e0 + e1 + e2 + e3 + f0 + f1 + f2 + f3;
#pragma unroll
        for (int off = 16; off > 0; off >>= 1)
            s += __shfl_xor_sync(0xffffffff, s, off);
        float inv = 1.0f / s;
        __half2* mrow = g_maskh + pr * 128;
        mrow[lane * 2 + 0] = __floats2half2_rn(e0 * inv, e1 * inv);
        mrow[lane * 2 + 1] = __floats2half2_rn(e2 * inv, e3 * inv);
        mrow[64 + lane * 2 + 0] = __floats2half2_rn(f0 * inv, f1 * inv);
        mrow[64 + lane * 2 + 1] = __floats2half2_rn(f2 * inv, f3 * inv);
    }
    if (t == 0) g_cnt[blockIdx.y] = 0;
}

// ---------------- K4: out[b] = mask @ xemb[b], fp16 mma ---------------------
// K-chunk 64 halves (32 u32), 4 iterations, 3 stages.
__device__ __forceinline__ void mma_f16(float c[4],
                                        uint32_t a0, uint32_t a1, uint32_t a2, uint32_t a3,
                                        uint32_t b0, uint32_t b1) {
    asm volatile(
        "mma.sync.aligned.m16n8k16.row.col.f32.f16.f16.f32 "
        "{%0,%1,%2,%3}, {%4,%5,%6,%7}, {%8,%9}, {%0,%1,%2,%3};"
        : "+f"(c[0]), "+f"(c[1]), "+f"(c[2]), "+f"(c[3])
        : "r"(a0), "r"(a1), "r"(a2), "r"(a3), "r"(b0), "r"(b1));
}

#define AS_STRIDE 36
#define BS_STRIDE 136
#define AS_BUF (128 * AS_STRIDE)
#define BS_BUF (32 * BS_STRIDE)
#define STAGE_U32 (AS_BUF + BS_BUF)
#define N_STAGES 3
#define GEMM_SMEM_BYTES (N_STAGES * STAGE_U32 * 4)   // 107520 B

__global__ __launch_bounds__(256, 2) void out_gemm_kernel(
    const float* __restrict__ ew,
    const float* __restrict__ eb,
    float* __restrict__ out) {
    extern __shared__ __align__(16) uint32_t smem[];

    int b = blockIdx.z;
    int m0 = blockIdx.y * 128;
    int n0 = blockIdx.x * 128;
    const uint32_t* A = (const uint32_t*)g_maskh;                     // [256][128]
    const uint32_t* B = (const uint32_t*)(g_xembh + (long)b * 32768); // [128][256]

    int tid = threadIdx.x;
    int lane = tid & 31;
    int warp = tid >> 5;
    int wm = (warp & 1) * 64;
    int wn = (warp >> 1) * 32;
    int grp = lane >> 2;
    int tig = lane & 3;

    int lrow = lane & 7;
    int lm = lane >> 3;
    int lds_row_off = lrow + ((lm & 1) << 3);
    int lds_col_off = (lm >> 1) << 2;

    float acc[4][4][4];
#pragma unroll
    for (int i = 0; i < 4; i++)
#pragma unroll
        for (int j = 0; j < 4; j++)
#pragma unroll
            for (int k = 0; k < 4; k++) acc[i][j][k] = 0.0f;

    auto load_tiles = [&](int stage, int kt) {
        uint32_t* As2 = smem + stage * STAGE_U32;
        uint32_t* Bs2 = As2 + AS_BUF;
        int kp0 = kt * 32;
#pragma unroll
        for (int t = 0; t < 4; t++) {
            int idx = t * 256 + tid;
            int r = idx >> 3;
            int kc = (idx & 7) << 2;
            cp_async16(&As2[r * AS_STRIDE + kc],
                       A + (m0 + r) * 128 + kp0 + kc);
        }
#pragma unroll
        for (int t = 0; t < 4; t++) {
            int idx = t * 256 + tid;
            int r = idx >> 5;
            int nc = (idx & 31) << 2;
            cp_async16(&Bs2[r * BS_STRIDE + nc],
                       B + (kp0 + r) * 256 + n0 + nc);
        }
        cp_commit();
    };

    load_tiles(0, 0);
    load_tiles(1, 1);
    load_tiles(2, 2);

#pragma unroll
    for (int kt = 0; kt < 4; kt++) {
        if (kt == 0)      { cp_wait<2>(); }
        else if (kt < 3)  { cp_wait<1>(); }
        else              { cp_wait<0>(); }
        __syncthreads();
        if (kt == 1) load_tiles(0, 3);

        int stage = kt % 3;
        const uint32_t* as = smem + stage * STAGE_U32;
        const uint32_t* bs = as + AS_BUF;
#pragma unroll
        for (int ks = 0; ks < 4; ks++) {
            int kk2 = ks * 8;
            uint32_t afr[4][4];
#pragma unroll
            for (int mi = 0; mi < 4; mi++) {
                int rb = wm + mi * 16 + lds_row_off;
                ldsm_x4(afr[mi][0], afr[mi][1], afr[mi][2], afr[mi][3],
                        &as[rb * AS_STRIDE + kk2 + lds_col_off]);
            }
            uint32_t bfr[4][2];
#pragma unroll
            for (int ni = 0; ni < 4; ni++) {
                int nb = wn + ni * 8 + grp;
                bfr[ni][0] = bs[(kk2 + tig) * BS_STRIDE + nb];
                bfr[ni][1] = bs[(kk2 + tig + 4) * BS_STRIDE + nb];
            }
#pragma unroll
            for (int mi = 0; mi < 4; mi++)
#pragma unroll
                for (int ni = 0; ni < 4; ni++)
                    mma_f16(acc[mi][ni],
                            afr[mi][0], afr[mi][1], afr[mi][2], afr[mi][3],
                            bfr[ni][0], bfr[ni][1]);
        }
    }

    // epilogue
    const __half2* maskb = g_maskh + b * 128;
    float ebb = eb[b];
#pragma unroll
    for (int mi = 0; mi < 4; mi++) {
#pragma unroll
        for (int h = 0; h < 2; h++) {
            int p = m0 + wm + mi * 16 + grp + h * 8;
            float scale = 1.0f + ew[p];
            __half2 mh = maskb[p >> 1];
            float mval = (p & 1) ? __high2float(mh) : __low2float(mh);
            float addv = mval * ebb;
            long rowoff = ((long)(b * 256 + p)) * 256;
#pragma unroll
            for (int ni = 0; ni < 4; ni++) {
                int d = n0 + wn + ni * 8 + tig * 2;
                float v0 = acc[mi][ni][h * 2 + 0] * scale + addv;
                float v1 = acc[mi][ni][h * 2 + 1] * scale + addv;
                *(float2*)(out + rowoff + d) = make_float2(v0, v1);
            }
        }
    }
}

// ---------------- launch -----------------------------------------------------
extern "C" void kernel_launch(void* const* d_in, const int* in_sizes, int n_in,
                              void* d_out, int out_size) {
    const float* x    = (const float*)d_in[0];
    const float* prev = (const float*)d_in[1];
    const float* few  = (const float*)d_in[2];
    const float* feb  = (const float*)d_in[3];
    const float* lnew = (const float*)d_in[4];
    const float* lneb = (const float*)d_in[5];
    const float* lncw = (const float*)d_in[6];
    const float* lncb = (const float*)d_in[7];
    const float* lnpw = (const float*)d_in[8];
    const float* lnpb = (const float*)d_in[9];
    const float* diw  = (const float*)d_in[10];
    const float* dib  = (const float*)d_in[11];
    const float* embc = (const float*)d_in[12];
    const float* embp = (const float*)d_in[13];
    const float* ew   = (const float*)d_in[14];
    const float* ebia = (const float*)d_in[15];
    float* out = (float*)d_out;

    static cudaStream_t s_chain;
    static cudaEvent_t ev_fork, ev_join;
    static bool init_done = false;
    if (!init_done) {
        cudaFuncSetAttribute(out_gemm_kernel,
                             cudaFuncAttributeMaxDynamicSharedMemorySize,
                             GEMM_SMEM_BYTES);
        cudaStreamCreateWithFlags(&s_chain, cudaStreamNonBlocking);
        cudaEventCreateWithFlags(&ev_fork, cudaEventDisableTiming);
        cudaEventCreateWithFlags(&ev_join, cudaEventDisableTiming);
        init_done = true;
    }

    cudaEventRecord(ev_fork, 0);
    cudaStreamWaitEvent(s_chain, ev_fork, 0);

    xprompt_fused<<<dim3(8, 16), dim3(16, 16), 0, s_chain>>>(diw, dib, embp,
                                                             lnpw, lnpb, prev);
    logits_fused<<<dim3(8, 16), dim3(16, 16), 0, s_chain>>>(embc, lncw, lncb);
    cudaEventRecord(ev_join, s_chain);

    xemb_kernel<<<4096, 256>>>(x, few, feb, lnew, lneb);

    cudaStreamWaitEvent(0, ev_join, 0);
    out_gemm_kernel<<<dim3(2, 2, 256), 256, GEMM_SMEM_BYTES>>>(ew, ebia, out);
}

// round 15
// speedup vs baseline: 1.0270x; 1.0270x over previous
#include <cuda_runtime.h>
#include <cuda_fp16.h>
#include <cstdint>

// Problem constants: B=C=P=D=256
#define N256 256
#define EPS 1e-5f

// ---------------- scratch (device globals; no allocations allowed) ----------
__device__ __half2 g_xembh[256 * 128 * 256]; // [b][c/2][d] k-pair-packed halves
__device__ __half2 g_maskh[256 * 128];       // [p][c/2] k-pair-packed halves
__device__ float g_xprompt[256 * 256];       // [P,D]
__device__ float g_logits[256 * 256];        // [P,C]
__device__ int g_cnt[8];                     // arrival counters (zero-init, self-resetting)

// ---------------- helpers ----------------------------------------------------
__device__ __forceinline__ void cp_async16(void* smem, const void* gmem) {
    uint32_t s = (uint32_t)__cvta_generic_to_shared(smem);
    asm volatile("cp.async.cg.shared.global [%0], [%1], 16;" :: "r"(s), "l"(gmem));
}
__device__ __forceinline__ void cp_commit() {
    asm volatile("cp.async.commit_group;" ::: "memory");
}
template <int N>
__device__ __forceinline__ void cp_wait() {
    asm volatile("cp.async.wait_group %0;" :: "n"(N) : "memory");
}
__device__ __forceinline__ void ldsm_x4(uint32_t& r0, uint32_t& r1,
                                        uint32_t& r2, uint32_t& r3,
                                        const void* smem_ptr) {
    uint32_t a = (uint32_t)__cvta_generic_to_shared(smem_ptr);
    asm volatile("ldmatrix.sync.aligned.m8n8.x4.shared.b16 {%0,%1,%2,%3}, [%4];"
                 : "=r"(r0), "=r"(r1), "=r"(r2), "=r"(r3) : "r"(a));
}

// per-32-row LN stats: 8 threads per row, 256 threads total.
__device__ __forceinline__ void row_stats_32(const float* __restrict__ src,
                                             int row0, float* smu, float* srs,
                                             int t) {
    int r = t >> 3, j = t & 7;
    const float4* base4 = (const float4*)(src + (row0 + r) * 256);
    float s = 0.f, q = 0.f;
#pragma unroll
    for (int i = 0; i < 8; i++) {
        float4 v = base4[j + i * 8];
        s += v.x + v.y + v.z + v.w;
        q = fmaf(v.x, v.x, q); q = fmaf(v.y, v.y, q);
        q = fmaf(v.z, v.z, q); q = fmaf(v.w, v.w, q);
    }
#pragma unroll
    for (int off = 4; off > 0; off >>= 1) {
        s += __shfl_xor_sync(0xffffffffu, s, off, 8);
        q += __shfl_xor_sync(0xffffffffu, q, off, 8);
    }
    if (j == 0) {
        float mu = s * (1.f / 256.f);
        smu[r] = mu;
        srs[r] = rsqrtf(q * (1.f / 256.f) - mu * mu + EPS);
    }
}

// ---------------- K1: xprompt (blocks 0..63) + xemb (blocks 64..4159) -------
// xprompt: x_prompt = [LN(embp)|prev] @ W^T + b + embp. 32x32 tiles, 2x2/thr.
// xemb: LN(relu(feb + x*few)) -> half2-packed [b][c/2][d].
__global__ void phase1_kernel(const float* __restrict__ x,
                              const float* __restrict__ few,
                              const float* __restrict__ feb,
                              const float* __restrict__ lnew,
                              const float* __restrict__ lneb,
                              const float* __restrict__ W,
                              const float* __restrict__ bias,
                              const float* __restrict__ embp,
                              const float* __restrict__ lnpw,
                              const float* __restrict__ lnpb,
                              const float* __restrict__ prev) {
    __shared__ float sbuf[6 * 256 + 64];
    int tid = threadIdx.x;
    if (blockIdx.x < 64) {
        // ---- xprompt tile (8 x 8 grid mapped from 64 blocks) ----
        float (*As)[17] = (float (*)[17])sbuf;                 // 32*17
        float (*Ws)[17] = (float (*)[17])(sbuf + 32 * 17);     // 32*17
        float* smu = sbuf + 64 * 17;
        float* srs = smu + 32;
        int tx = tid & 15, ty = tid >> 4;
        int p0 = (blockIdx.x >> 3) * 32;
        int d0 = (blockIdx.x & 7) * 32;

        row_stats_32(embp, p0, smu, srs, tid);
        __syncthreads();

        int r0 = tid >> 4, k0i = tid & 15;
        int r1 = 16 + r0;

        auto fetch = [&](int kt, float* v, float* w) {
            int kb = kt * 16;
            int gk = kb + k0i;
            v[0] = (gk < 256)
                 ? (embp[(p0 + r0) * 256 + gk] - smu[r0]) * srs[r0] * lnpw[gk] + lnpb[gk]
                 : prev[(p0 + r0) * 256 + gk - 256];
            v[1] = (gk < 256)
                 ? (embp[(p0 + r1) * 256 + gk] - smu[r1]) * srs[r1] * lnpw[gk] + lnpb[gk]
                 : prev[(p0 + r1) * 256 + gk - 256];
            w[0] = W[(d0 + r0) * 512 + gk];
            w[1] = W[(d0 + r1) * 512 + gk];
        };

        float va[2], wa[2], vb[2], wb[2];
        fetch(0, va, wa);

        float acc[2][2] = {{0.f, 0.f}, {0.f, 0.f}};
        for (int kt = 0; kt < 32; kt++) {
            As[r0][k0i] = va[0]; Ws[r0][k0i] = wa[0];
            As[r1][k0i] = va[1]; Ws[r1][k0i] = wa[1];
            __syncthreads();
            if (kt < 31) fetch(kt + 1, vb, wb);
#pragma unroll
            for (int kk = 0; kk < 16; kk++) {
                float a0 = As[ty * 2][kk], a1 = As[ty * 2 + 1][kk];
                float b0 = Ws[tx * 2][kk], b1 = Ws[tx * 2 + 1][kk];
                acc[0][0] += a0 * b0; acc[0][1] += a0 * b1;
                acc[1][0] += a1 * b0; acc[1][1] += a1 * b1;
            }
            __syncthreads();
            va[0] = vb[0]; va[1] = vb[1]; wa[0] = wb[0]; wa[1] = wb[1];
        }
#pragma unroll
        for (int i = 0; i < 2; i++)
#pragma unroll
            for (int j = 0; j < 2; j++) {
                int p = p0 + ty * 2 + i, dd = d0 + tx * 2 + j;
                g_xprompt[p * N256 + dd] = acc[i][j] + bias[dd] + embp[p * N256 + dd];
            }
    } else {
        // ---- xemb c-pair block ----
        float* sw0 = sbuf;
        float* sb0 = sbuf + 256;
        float* sw1 = sbuf + 512;
        float* sb1 = sbuf + 768;
        float* slw = sbuf + 1024;
        float* slb = sbuf + 1280;
        int blk = blockIdx.x - 64;
        int c2 = blk >> 5;
        int bg = blk & 31;
        int c0 = c2 * 2, c1 = c0 + 1;
        sw0[tid] = few[c0 * 256 + tid];
        sb0[tid] = feb[c0 * 256 + tid];
        sw1[tid] = few[c1 * 256 + tid];
        sb1[tid] = feb[c1 * 256 + tid];
        slw[tid] = lnew[tid];
        slb[tid] = lneb[tid];
        __syncthreads();

        int lane = tid & 31;
        int wid = tid >> 5;
        int b = bg * 8 + wid;
        float xv0 = x[b * 256 + c0];
        float xv1 = x[b * 256 + c1];
        float v0[8], v1[8];
        float s0 = 0.f, q0 = 0.f, s1 = 0.f, q1 = 0.f;
#pragma unroll
        for (int i = 0; i < 8; i++) {
            int d = lane + i * 32;
            float t0 = fmaf(xv0, sw0[d], sb0[d]);
            float t1 = fmaf(xv1, sw1[d], sb1[d]);
            t0 = t0 > 0.f ? t0 : 0.f;
            t1 = t1 > 0.f ? t1 : 0.f;
            v0[i] = t0; v1[i] = t1;
            s0 += t0; q0 = fmaf(t0, t0, q0);
            s1 += t1; q1 = fmaf(t1, t1, q1);
        }
#pragma unroll
        for (int off = 16; off > 0; off >>= 1) {
            s0 += __shfl_xor_sync(0xffffffff, s0, off);
            q0 += __shfl_xor_sync(0xffffffff, q0, off);
            s1 += __shfl_xor_sync(0xffffffff, s1, off);
            q1 += __shfl_xor_sync(0xffffffff, q1, off);
        }
        float mu0 = s0 * (1.f / 256.f);
        float rs0 = rsqrtf(q0 * (1.f / 256.f) - mu0 * mu0 + EPS);
        float mu1 = s1 * (1.f / 256.f);
        float rs1 = rsqrtf(q1 * (1.f / 256.f) - mu1 * mu1 + EPS);
        __half2* orow = g_xembh + ((long)b * 128 + c2) * 256;
#pragma unroll
        for (int i = 0; i < 8; i++) {
            int d = lane + i * 32;
            float o0 = (v0[i] - mu0) * rs0 * slw[d] + slb[d];
            float o1 = (v1[i] - mu1) * rs1 * slw[d] + slb[d];
            orow[d] = __floats2half2_rn(o0, o1);
        }
    }
}

// ---------------- K2: logits = x_prompt @ LN(embc)^T, softmax fused ----------
// 32x32 tiles (grid 8x8), 2x2/thread; last block per 32-row group does softmax.
__global__ void logits_fused(const float* __restrict__ embc,
                             const float* __restrict__ lncw,
                             const float* __restrict__ lncb) {
    __shared__ float As[32][17];
    __shared__ float Bs[32][17];
    __shared__ float smu[32], srs[32];
    __shared__ int sflag;
    int tx = threadIdx.x, ty = threadIdx.y;
    int t = ty * 16 + tx;
    int p0 = blockIdx.y * 32;
    int c0 = blockIdx.x * 32;

    row_stats_32(embc, c0, smu, srs, t);
    __syncthreads();

    int r0 = t >> 4, k0i = t & 15;
    int r1 = 16 + r0;

    auto fetch = [&](int kt, float* a, float* b) {
        int gk = kt * 16 + k0i;
        a[0] = g_xprompt[(p0 + r0) * N256 + gk];
        a[1] = g_xprompt[(p0 + r1) * N256 + gk];
        b[0] = (embc[(c0 + r0) * 256 + gk] - smu[r0]) * srs[r0] * lncw[gk] + lncb[gk];
        b[1] = (embc[(c0 + r1) * 256 + gk] - smu[r1]) * srs[r1] * lncw[gk] + lncb[gk];
    };

    float aa[2], ba[2], ab[2], bb[2];
    fetch(0, aa, ba);

    float acc[2][2] = {{0.f, 0.f}, {0.f, 0.f}};
    for (int kt = 0; kt < 16; kt++) {
        As[r0][k0i] = aa[0]; Bs[r0][k0i] = ba[0];
        As[r1][k0i] = aa[1]; Bs[r1][k0i] = ba[1];
        __syncthreads();
        if (kt < 15) fetch(kt + 1, ab, bb);
#pragma unroll
        for (int kk = 0; kk < 16; kk++) {
            float a0 = As[ty * 2][kk], a1 = As[ty * 2 + 1][kk];
            float b0 = Bs[tx * 2][kk], b1 = Bs[tx * 2 + 1][kk];
            acc[0][0] += a0 * b0; acc[0][1] += a0 * b1;
            acc[1][0] += a1 * b0; acc[1][1] += a1 * b1;
        }
        __syncthreads();
        aa[0] = ab[0]; aa[1] = ab[1]; ba[0] = bb[0]; ba[1] = bb[1];
    }
#pragma unroll
    for (int i = 0; i < 2; i++)
#pragma unroll
        for (int j = 0; j < 2; j++)
            g_logits[(p0 + ty * 2 + i) * N256 + c0 + tx * 2 + j] = acc[i][j];

    __threadfence();
    __syncthreads();
    if (t == 0) {
        int old = atomicAdd(&g_cnt[blockIdx.y], 1);
        sflag = (old == 7);
    }
    __syncthreads();
    if (!sflag) return;

    int lane = t & 31;
    int warp = t >> 5;
#pragma unroll
    for (int q = 0; q < 4; q++) {
        int p = p0 + warp * 4 + q;
        const float* row = g_logits + p * N256;
        float4 v0 = *(const float4*)(row + lane * 4);
        float4 v1 = *(const float4*)(row + 128 + lane * 4);
        float m = fmaxf(fmaxf(fmaxf(v0.x, v0.y), fmaxf(v0.z, v0.w)),
                        fmaxf(fmaxf(v1.x, v1.y), fmaxf(v1.z, v1.w)));
#pragma unroll
        for (int off = 16; off > 0; off >>= 1)
            m = fmaxf(m, __shfl_xor_sync(0xffffffff, m, off));
        float e0 = expf(v0.x - m), e1 = expf(v0.y - m);
        float e2 = expf(v0.z - m), e3 = expf(v0.w - m);
        float f0 = expf(v1.x - m), f1 = expf(v1.y - m);
        float f2 = expf(v1.z - m), f3 = expf(v1.w - m);
        float s = e0 + e1 + e2 + e3 + f0 + f1 + f2 + f3;
#pragma unroll
        for (int off = 16; off > 0; off >>= 1)
            s += __shfl_xor_sync(0xffffffff, s, off);
        float inv = 1.0f / s;
        __half2* mrow = g_maskh + p * 128;
        mrow[lane * 2 + 0] = __floats2half2_rn(e0 * inv, e1 * inv);
        mrow[lane * 2 + 1] = __floats2half2_rn(e2 * inv, e3 * inv);
        mrow[64 + lane * 2 + 0] = __floats2half2_rn(f0 * inv, f1 * inv);
        mrow[64 + lane * 2 + 1] = __floats2half2_rn(f2 * inv, f3 * inv);
    }
    if (t == 0) g_cnt[blockIdx.y] = 0;
}

// ---------------- K3: out[b] = mask @ xemb[b], fp16 mma ---------------------
// K-chunk 64 halves (32 u32), 4 iterations, 3 stages.
__device__ __forceinline__ void mma_f16(float c[4],
                                        uint32_t a0, uint32_t a1, uint32_t a2, uint32_t a3,
                                        uint32_t b0, uint32_t b1) {
    asm volatile(
        "mma.sync.aligned.m16n8k16.row.col.f32.f16.f16.f32 "
        "{%0,%1,%2,%3}, {%4,%5,%6,%7}, {%8,%9}, {%0,%1,%2,%3};"
        : "+f"(c[0]), "+f"(c[1]), "+f"(c[2]), "+f"(c[3])
        : "r"(a0), "r"(a1), "r"(a2), "r"(a3), "r"(b0), "r"(b1));
}

#define AS_STRIDE 36
#define BS_STRIDE 136
#define AS_BUF (128 * AS_STRIDE)
#define BS_BUF (32 * BS_STRIDE)
#define STAGE_U32 (AS_BUF + BS_BUF)
#define N_STAGES 3
#define GEMM_SMEM_BYTES (N_STAGES * STAGE_U32 * 4)   // 107520 B

__global__ __launch_bounds__(256, 2) void out_gemm_kernel(
    const float* __restrict__ ew,
    const float* __restrict__ eb,
    float* __restrict__ out) {
    extern __shared__ __align__(16) uint32_t smem[];

    int b = blockIdx.z;
    int m0 = blockIdx.y * 128;
    int n0 = blockIdx.x * 128;
    const uint32_t* A = (const uint32_t*)g_maskh;                     // [256][128]
    const uint32_t* B = (const uint32_t*)(g_xembh + (long)b * 32768); // [128][256]

    int tid = threadIdx.x;
    int lane = tid & 31;
    int warp = tid >> 5;
    int wm = (warp & 1) * 64;
    int wn = (warp >> 1) * 32;
    int grp = lane >> 2;
    int tig = lane & 3;

    int lrow = lane & 7;
    int lm = lane >> 3;
    int lds_row_off = lrow + ((lm & 1) << 3);
    int lds_col_off = (lm >> 1) << 2;

    float acc[4][4][4];
#pragma unroll
    for (int i = 0; i < 4; i++)
#pragma unroll
        for (int j = 0; j < 4; j++)
#pragma unroll
            for (int k = 0; k < 4; k++) acc[i][j][k] = 0.0f;

    auto load_tiles = [&](int stage, int kt) {
        uint32_t* As2 = smem + stage * STAGE_U32;
        uint32_t* Bs2 = As2 + AS_BUF;
        int kp0 = kt * 32;
#pragma unroll
        for (int t = 0; t < 4; t++) {
            int idx = t * 256 + tid;
            int r = idx >> 3;
            int kc = (idx & 7) << 2;
            cp_async16(&As2[r * AS_STRIDE + kc],
                       A + (m0 + r) * 128 + kp0 + kc);
        }
#pragma unroll
        for (int t = 0; t < 4; t++) {
            int idx = t * 256 + tid;
            int r = idx >> 5;
            int nc = (idx & 31) << 2;
            cp_async16(&Bs2[r * BS_STRIDE + nc],
                       B + (kp0 + r) * 256 + n0 + nc);
        }
        cp_commit();
    };

    load_tiles(0, 0);
    load_tiles(1, 1);
    load_tiles(2, 2);

#pragma unroll
    for (int kt = 0; kt < 4; kt++) {
        if (kt == 0)      { cp_wait<2>(); }
        else if (kt < 3)  { cp_wait<1>(); }
        else              { cp_wait<0>(); }
        __syncthreads();
        if (kt == 1) load_tiles(0, 3);

        int stage = kt % 3;
        const uint32_t* as = smem + stage * STAGE_U32;
        const uint32_t* bs = as + AS_BUF;
#pragma unroll
        for (int ks = 0; ks < 4; ks++) {
            int kk2 = ks * 8;
            uint32_t afr[4][4];
#pragma unroll
            for (int mi = 0; mi < 4; mi++) {
                int rb = wm + mi * 16 + lds_row_off;
                ldsm_x4(afr[mi][0], afr[mi][1], afr[mi][2], afr[mi][3],
                        &as[rb * AS_STRIDE + kk2 + lds_col_off]);
            }
            uint32_t bfr[4][2];
#pragma unroll
            for (int ni = 0; ni < 4; ni++) {
                int nb = wn + ni * 8 + grp;
                bfr[ni][0] = bs[(kk2 + tig) * BS_STRIDE + nb];
                bfr[ni][1] = bs[(kk2 + tig + 4) * BS_STRIDE + nb];
            }
#pragma unroll
            for (int mi = 0; mi < 4; mi++)
#pragma unroll
                for (int ni = 0; ni < 4; ni++)
                    mma_f16(acc[mi][ni],
                            afr[mi][0], afr[mi][1], afr[mi][2], afr[mi][3],
                            bfr[ni][0], bfr[ni][1]);
        }
    }

    // epilogue
    const __half2* maskb = g_maskh + b * 128;
    float ebb = eb[b];
#pragma unroll
    for (int mi = 0; mi < 4; mi++) {
#pragma unroll
        for (int h = 0; h < 2; h++) {
            int p = m0 + wm + mi * 16 + grp + h * 8;
            float scale = 1.0f + ew[p];
            __half2 mh = maskb[p >> 1];
            float mval = (p & 1) ? __high2float(mh) : __low2float(mh);
            float addv = mval * ebb;
            long rowoff = ((long)(b * 256 + p)) * 256;
#pragma unroll
            for (int ni = 0; ni < 4; ni++) {
                int d = n0 + wn + ni * 8 + tig * 2;
                float v0 = acc[mi][ni][h * 2 + 0] * scale + addv;
                float v1 = acc[mi][ni][h * 2 + 1] * scale + addv;
                *(float2*)(out + rowoff + d) = make_float2(v0, v1);
            }
        }
    }
}

// ---------------- launch -----------------------------------------------------
extern "C" void kernel_launch(void* const* d_in, const int* in_sizes, int n_in,
                              void* d_out, int out_size) {
    const float* x    = (const float*)d_in[0];
    const float* prev = (const float*)d_in[1];
    const float* few  = (const float*)d_in[2];
    const float* feb  = (const float*)d_in[3];
    const float* lnew = (const float*)d_in[4];
    const float* lneb = (const float*)d_in[5];
    const float* lncw = (const float*)d_in[6];
    const float* lncb = (const float*)d_in[7];
    const float* lnpw = (const float*)d_in[8];
    const float* lnpb = (const float*)d_in[9];
    const float* diw  = (const float*)d_in[10];
    const float* dib  = (const float*)d_in[11];
    const float* embc = (const float*)d_in[12];
    const float* embp = (const float*)d_in[13];
    const float* ew   = (const float*)d_in[14];
    const float* ebia = (const float*)d_in[15];
    float* out = (float*)d_out;

    static bool init_done = false;
    if (!init_done) {
        cudaFuncSetAttribute(out_gemm_kernel,
                             cudaFuncAttributeMaxDynamicSharedMemorySize,
                             GEMM_SMEM_BYTES);
        init_done = true;
    }

    phase1_kernel<<<4160, 256>>>(x, few, feb, lnew, lneb,
                                 diw, dib, embp, lnpw, lnpb, prev);
    logits_fused<<<dim3(8, 8), dim3(16, 16)>>>(embc, lncw, lncb);
    out_gemm_kernel<<<dim3(2, 2, 256), 256, GEMM_SMEM_BYTES>>>(ew, ebia, out);
}